// round 2
// baseline (speedup 1.0000x reference)
#include <cuda_runtime.h>
#include <cstdint>

// Problem constants
#define NB 192            // subgraphs
#define SS 512            // nodes per subgraph
#define EE 128            // embed
#define NROWS (NB*SS)     // 98304

// Scratch layout (floats)
#define SZ_MAT ((size_t)NROWS*EE)           // 12,582,912
#define OFF_XS  ((size_t)0)
#define OFF_Q   (SZ_MAT*1)
#define OFF_K   (SZ_MAT*2)
#define OFF_V   (SZ_MAT*3)
#define OFF_ATT (SZ_MAT*4)
#define OFF_HS  (SZ_MAT*5)
#define OFF_DOT (SZ_MAT*6)                  // 192*512*512 = 50,331,648
#define SZ_DOT  ((size_t)NB*SS*SS)
#define OFF_RS  (OFF_DOT + SZ_DOT)          // rscale per row
#define SCRATCH_FLOATS (OFF_RS + NROWS)

__device__ __align__(256) float g_scratch[SCRATCH_FLOATS];

// ---------------------------------------------------------------------------
// LayerNorm (no affine) + ReLU, one warp per 128-elem row
// ---------------------------------------------------------------------------
__global__ __launch_bounds__(256) void ln_relu_kernel(const float* __restrict__ in,
                                                      float* __restrict__ out) {
    int row  = blockIdx.x * 8 + (threadIdx.x >> 5);
    int lane = threadIdx.x & 31;
    const float4* p = reinterpret_cast<const float4*>(in + (size_t)row * EE);
    float4 a = p[lane];
    float s = a.x + a.y + a.z + a.w;
    #pragma unroll
    for (int o = 16; o; o >>= 1) s += __shfl_xor_sync(0xffffffffu, s, o);
    float mean = s * (1.0f / 128.0f);
    float dx = a.x - mean, dy = a.y - mean, dz = a.z - mean, dw = a.w - mean;
    float q = dx*dx + dy*dy + dz*dz + dw*dw;
    #pragma unroll
    for (int o = 16; o; o >>= 1) q += __shfl_xor_sync(0xffffffffu, q, o);
    float inv = rsqrtf(q * (1.0f / 128.0f) + 1e-5f);
    float4 r;
    r.x = fmaxf(dx * inv, 0.0f);
    r.y = fmaxf(dy * inv, 0.0f);
    r.z = fmaxf(dz * inv, 0.0f);
    r.w = fmaxf(dw * inv, 0.0f);
    reinterpret_cast<float4*>(out + (size_t)row * EE)[lane] = r;
}

// ---------------------------------------------------------------------------
// Row degree of adj -> rsqrt(deg), one warp per 512-elem row
// ---------------------------------------------------------------------------
__global__ __launch_bounds__(256) void deg_kernel(const float* __restrict__ adj,
                                                  float* __restrict__ rscale) {
    int row  = blockIdx.x * 8 + (threadIdx.x >> 5);
    int lane = threadIdx.x & 31;
    const float4* p = reinterpret_cast<const float4*>(adj + (size_t)row * SS);
    float s = 0.0f;
    #pragma unroll
    for (int i = 0; i < 4; i++) {
        float4 a = p[lane + 32 * i];
        s += a.x + a.y + a.z + a.w;
    }
    #pragma unroll
    for (int o = 16; o; o >>= 1) s += __shfl_xor_sync(0xffffffffu, s, o);
    if (lane == 0) rscale[row] = rsqrtf(s);
}

// ---------------------------------------------------------------------------
// TN GEMM: C[M,128] = A[M,128] @ W[128,128]^T (+bias) (+residual)
// BM=BN=128, BK=16, 256 threads, 8x8 strided fragments per thread.
// RES=0: C = acc + bias; RES=1: C = res + acc + bias
// ---------------------------------------------------------------------------
template <int RES>
__global__ __launch_bounds__(256) void gemm_tn_kernel(const float* __restrict__ A,
                                                      const float* __restrict__ W,
                                                      const float* __restrict__ bias,
                                                      float* __restrict__ C,
                                                      const float* __restrict__ res) {
    __shared__ float As[16][EE + 4];
    __shared__ float Ws[16][EE + 4];
    const int tid = threadIdx.x;
    const int m0  = blockIdx.x * 128;
    const int tx  = tid & 15;
    const int ty  = tid >> 4;
    const int lm  = tid >> 1;
    const int lkb = (tid & 1) * 8;

    float acc[8][8];
    #pragma unroll
    for (int i = 0; i < 8; i++)
        #pragma unroll
        for (int j = 0; j < 8; j++) acc[i][j] = 0.0f;

    for (int k0 = 0; k0 < 128; k0 += 16) {
        float4 a0 = *reinterpret_cast<const float4*>(A + (size_t)(m0 + lm) * EE + k0 + lkb);
        float4 a1 = *reinterpret_cast<const float4*>(A + (size_t)(m0 + lm) * EE + k0 + lkb + 4);
        float4 w0 = *reinterpret_cast<const float4*>(W + (size_t)lm * EE + k0 + lkb);
        float4 w1 = *reinterpret_cast<const float4*>(W + (size_t)lm * EE + k0 + lkb + 4);
        As[lkb + 0][lm] = a0.x; As[lkb + 1][lm] = a0.y; As[lkb + 2][lm] = a0.z; As[lkb + 3][lm] = a0.w;
        As[lkb + 4][lm] = a1.x; As[lkb + 5][lm] = a1.y; As[lkb + 6][lm] = a1.z; As[lkb + 7][lm] = a1.w;
        Ws[lkb + 0][lm] = w0.x; Ws[lkb + 1][lm] = w0.y; Ws[lkb + 2][lm] = w0.z; Ws[lkb + 3][lm] = w0.w;
        Ws[lkb + 4][lm] = w1.x; Ws[lkb + 5][lm] = w1.y; Ws[lkb + 6][lm] = w1.z; Ws[lkb + 7][lm] = w1.w;
        __syncthreads();
        #pragma unroll
        for (int kk = 0; kk < 16; kk++) {
            float ar[8], br[8];
            #pragma unroll
            for (int i = 0; i < 8; i++) ar[i] = As[kk][ty + 16 * i];
            #pragma unroll
            for (int j = 0; j < 8; j++) br[j] = Ws[kk][tx + 16 * j];
            #pragma unroll
            for (int i = 0; i < 8; i++)
                #pragma unroll
                for (int j = 0; j < 8; j++) acc[i][j] = fmaf(ar[i], br[j], acc[i][j]);
        }
        __syncthreads();
    }

    float bv[8];
    #pragma unroll
    for (int j = 0; j < 8; j++) bv[j] = bias[tx + 16 * j];
    #pragma unroll
    for (int i = 0; i < 8; i++) {
        size_t m = (size_t)(m0 + ty + 16 * i);
        #pragma unroll
        for (int j = 0; j < 8; j++) {
            int n = tx + 16 * j;
            float v = acc[i][j] + bv[j];
            if (RES) v += res[m * EE + n];
            C[m * EE + n] = v;
        }
    }
}

// ---------------------------------------------------------------------------
// Batched scores: dot[b] tile (128q x 128k) = q @ k^T, epilogue scale+mask
// grid: (4 qtiles, 4 ktiles, 192 b)
// ---------------------------------------------------------------------------
__global__ __launch_bounds__(256) void gemm_dot_kernel(const float* __restrict__ Qm,
                                                       const float* __restrict__ Km,
                                                       const float* __restrict__ adj,
                                                       const float* __restrict__ rscale,
                                                       float* __restrict__ dot) {
    __shared__ float As[16][EE + 4];
    __shared__ float Bs[16][EE + 4];
    const int b = blockIdx.z;
    const float* A  = Qm + (size_t)b * SS * EE + (size_t)blockIdx.x * 128 * EE;
    const float* Bm = Km + (size_t)b * SS * EE + (size_t)blockIdx.y * 128 * EE;
    const int tid = threadIdx.x;
    const int tx  = tid & 15;
    const int ty  = tid >> 4;
    const int lm  = tid >> 1;
    const int lkb = (tid & 1) * 8;

    float acc[8][8];
    #pragma unroll
    for (int i = 0; i < 8; i++)
        #pragma unroll
        for (int j = 0; j < 8; j++) acc[i][j] = 0.0f;

    for (int k0 = 0; k0 < 128; k0 += 16) {
        float4 a0 = *reinterpret_cast<const float4*>(A + (size_t)lm * EE + k0 + lkb);
        float4 a1 = *reinterpret_cast<const float4*>(A + (size_t)lm * EE + k0 + lkb + 4);
        float4 w0 = *reinterpret_cast<const float4*>(Bm + (size_t)lm * EE + k0 + lkb);
        float4 w1 = *reinterpret_cast<const float4*>(Bm + (size_t)lm * EE + k0 + lkb + 4);
        As[lkb + 0][lm] = a0.x; As[lkb + 1][lm] = a0.y; As[lkb + 2][lm] = a0.z; As[lkb + 3][lm] = a0.w;
        As[lkb + 4][lm] = a1.x; As[lkb + 5][lm] = a1.y; As[lkb + 6][lm] = a1.z; As[lkb + 7][lm] = a1.w;
        Bs[lkb + 0][lm] = w0.x; Bs[lkb + 1][lm] = w0.y; Bs[lkb + 2][lm] = w0.z; Bs[lkb + 3][lm] = w0.w;
        Bs[lkb + 4][lm] = w1.x; Bs[lkb + 5][lm] = w1.y; Bs[lkb + 6][lm] = w1.z; Bs[lkb + 7][lm] = w1.w;
        __syncthreads();
        #pragma unroll
        for (int kk = 0; kk < 16; kk++) {
            float ar[8], br[8];
            #pragma unroll
            for (int i = 0; i < 8; i++) ar[i] = As[kk][ty + 16 * i];
            #pragma unroll
            for (int j = 0; j < 8; j++) br[j] = Bs[kk][tx + 16 * j];
            #pragma unroll
            for (int i = 0; i < 8; i++)
                #pragma unroll
                for (int j = 0; j < 8; j++) acc[i][j] = fmaf(ar[i], br[j], acc[i][j]);
        }
        __syncthreads();
    }

    #pragma unroll
    for (int i = 0; i < 8; i++) {
        int qi = blockIdx.x * 128 + ty + 16 * i;
        size_t grow = (size_t)b * SS + qi;
        float rs = rscale[grow];
        #pragma unroll
        for (int j = 0; j < 8; j++) {
            int kj = blockIdx.y * 128 + tx + 16 * j;
            float aval = adj[grow * SS + kj];
            float v = (aval != 0.0f) ? acc[i][j] * rs : -1e30f;
            dot[grow * SS + kj] = v;
        }
    }
}

// ---------------------------------------------------------------------------
// Row softmax over 512 cols, one warp per row (in place)
// ---------------------------------------------------------------------------
__global__ __launch_bounds__(256) void softmax_kernel(float* __restrict__ dot) {
    int row  = blockIdx.x * 8 + (threadIdx.x >> 5);
    int lane = threadIdx.x & 31;
    float4* p = reinterpret_cast<float4*>(dot + (size_t)row * SS);
    float4 v[4];
    float m = -3.4e38f;
    #pragma unroll
    for (int i = 0; i < 4; i++) {
        v[i] = p[lane + 32 * i];
        m = fmaxf(m, fmaxf(fmaxf(v[i].x, v[i].y), fmaxf(v[i].z, v[i].w)));
    }
    #pragma unroll
    for (int o = 16; o; o >>= 1) m = fmaxf(m, __shfl_xor_sync(0xffffffffu, m, o));
    float s = 0.0f;
    #pragma unroll
    for (int i = 0; i < 4; i++) {
        v[i].x = __expf(v[i].x - m);
        v[i].y = __expf(v[i].y - m);
        v[i].z = __expf(v[i].z - m);
        v[i].w = __expf(v[i].w - m);
        s += v[i].x + v[i].y + v[i].z + v[i].w;
    }
    #pragma unroll
    for (int o = 16; o; o >>= 1) s += __shfl_xor_sync(0xffffffffu, s, o);
    float inv = 1.0f / s;
    #pragma unroll
    for (int i = 0; i < 4; i++) {
        v[i].x *= inv; v[i].y *= inv; v[i].z *= inv; v[i].w *= inv;
        p[lane + 32 * i] = v[i];
    }
}

// ---------------------------------------------------------------------------
// Batched NN GEMM: out[b, q0:q0+128, :] = attn[b, q0:q0+128, :512] @ v[b]
// grid: (4 qtiles, 192 b). K=512, BK=16.
// ---------------------------------------------------------------------------
__global__ __launch_bounds__(256) void gemm_av_kernel(const float* __restrict__ P,
                                                      const float* __restrict__ V,
                                                      float* __restrict__ O) {
    __shared__ float As[16][EE + 4];
    __shared__ float Bs[16][EE + 4];
    const int b = blockIdx.y;
    const float* A  = P + (size_t)b * SS * SS + (size_t)blockIdx.x * 128 * SS;
    const float* Bm = V + (size_t)b * SS * EE;
    const int tid = threadIdx.x;
    const int tx  = tid & 15;
    const int ty  = tid >> 4;
    const int lm  = tid >> 1;          // A: row within tile
    const int lkb = (tid & 1) * 8;     // A: k offset
    const int bk  = tid >> 4;          // B: k row (0..15)
    const int bn  = (tid & 15) * 8;    // B: col base

    float acc[8][8];
    #pragma unroll
    for (int i = 0; i < 8; i++)
        #pragma unroll
        for (int j = 0; j < 8; j++) acc[i][j] = 0.0f;

    for (int k0 = 0; k0 < SS; k0 += 16) {
        float4 a0 = *reinterpret_cast<const float4*>(A + (size_t)lm * SS + k0 + lkb);
        float4 a1 = *reinterpret_cast<const float4*>(A + (size_t)lm * SS + k0 + lkb + 4);
        float4 b0 = *reinterpret_cast<const float4*>(Bm + (size_t)(k0 + bk) * EE + bn);
        float4 b1 = *reinterpret_cast<const float4*>(Bm + (size_t)(k0 + bk) * EE + bn + 4);
        As[lkb + 0][lm] = a0.x; As[lkb + 1][lm] = a0.y; As[lkb + 2][lm] = a0.z; As[lkb + 3][lm] = a0.w;
        As[lkb + 4][lm] = a1.x; As[lkb + 5][lm] = a1.y; As[lkb + 6][lm] = a1.z; As[lkb + 7][lm] = a1.w;
        *reinterpret_cast<float4*>(&Bs[bk][bn])     = b0;
        *reinterpret_cast<float4*>(&Bs[bk][bn + 4]) = b1;
        __syncthreads();
        #pragma unroll
        for (int kk = 0; kk < 16; kk++) {
            float ar[8], br[8];
            #pragma unroll
            for (int i = 0; i < 8; i++) ar[i] = As[kk][ty + 16 * i];
            #pragma unroll
            for (int j = 0; j < 8; j++) br[j] = Bs[kk][tx + 16 * j];
            #pragma unroll
            for (int i = 0; i < 8; i++)
                #pragma unroll
                for (int j = 0; j < 8; j++) acc[i][j] = fmaf(ar[i], br[j], acc[i][j]);
        }
        __syncthreads();
    }

    #pragma unroll
    for (int i = 0; i < 8; i++) {
        size_t m = (size_t)b * SS + blockIdx.x * 128 + ty + 16 * i;
        #pragma unroll
        for (int j = 0; j < 8; j++) {
            O[m * EE + tx + 16 * j] = acc[i][j];
        }
    }
}

// ---------------------------------------------------------------------------
extern "C" void kernel_launch(void* const* d_in, const int* in_sizes, int n_in,
                              void* d_out, int out_size) {
    const float* x   = (const float*)d_in[0];
    const float* adj = (const float*)d_in[1];
    const float* Wq  = (const float*)d_in[2];
    const float* bq  = (const float*)d_in[3];
    const float* Wk  = (const float*)d_in[4];
    const float* bk  = (const float*)d_in[5];
    const float* Wv  = (const float*)d_in[6];
    const float* bv  = (const float*)d_in[7];
    const float* Wo  = (const float*)d_in[8];
    const float* bo  = (const float*)d_in[9];
    float* out = (float*)d_out;

    float* s = nullptr;
    cudaGetSymbolAddress((void**)&s, g_scratch);
    float* xs  = s + OFF_XS;
    float* q   = s + OFF_Q;
    float* k   = s + OFF_K;
    float* v   = s + OFF_V;
    float* att = s + OFF_ATT;
    float* hs  = s + OFF_HS;
    float* dot = s + OFF_DOT;
    float* rs  = s + OFF_RS;

    // 1. setup: LN + ReLU
    ln_relu_kernel<<<NROWS / 8, 256>>>(x, xs);
    // 2. deg -> rsqrt
    deg_kernel<<<NROWS / 8, 256>>>(adj, rs);
    // 3. QKV projections
    gemm_tn_kernel<0><<<NROWS / 128, 256>>>(xs, Wq, bq, q, nullptr);
    gemm_tn_kernel<0><<<NROWS / 128, 256>>>(xs, Wk, bk, k, nullptr);
    gemm_tn_kernel<0><<<NROWS / 128, 256>>>(xs, Wv, bv, v, nullptr);
    // 4. scores + scale + mask
    gemm_dot_kernel<<<dim3(SS / 128, SS / 128, NB), 256>>>(q, k, adj, rs, dot);
    // 5. softmax
    softmax_kernel<<<NROWS / 8, 256>>>(dot);
    // 6. attn @ v
    gemm_av_kernel<<<dim3(SS / 128, NB), 256>>>(dot, v, att);
    // 7. LN + ReLU
    ln_relu_kernel<<<NROWS / 8, 256>>>(att, hs);
    // 8. out = x + hs @ Wo^T + bo
    gemm_tn_kernel<1><<<NROWS / 128, 256>>>(hs, Wo, bo, out, x);
}

// round 4
// speedup vs baseline: 1.7769x; 1.7769x over previous
#include <cuda_runtime.h>
#include <cuda_bf16.h>
#include <cstdint>

#define NB 192
#define SS 512
#define EE 128
#define NROWS (NB*SS)

// ---------------- scratch (bytes) ----------------
#define B_MAT ((size_t)NROWS*EE*2)          // bf16 [NROWS,128]
#define B_ATT ((size_t)NB*SS*SS*2)          // bf16 [NB,512,512]
#define O_XS_HI  ((size_t)0)
#define O_XS_LO  (O_XS_HI + B_MAT)
#define O_Q_HI   (O_XS_LO + B_MAT)
#define O_Q_LO   (O_Q_HI + B_MAT)
#define O_K_HI   (O_Q_LO + B_MAT)
#define O_K_LO   (O_K_HI + B_MAT)
#define O_VT_HI  (O_K_LO + B_MAT)
#define O_VT_LO  (O_VT_HI + B_MAT)
#define O_HS_HI  (O_VT_LO + B_MAT)
#define O_HS_LO  (O_HS_HI + B_MAT)
#define O_PH     (O_HS_LO + B_MAT)
#define O_PL     (O_PH + B_ATT)
#define O_DOT    (O_PL + B_ATT)                       // fp32 scores
#define O_ATTO   (O_DOT + (size_t)NB*SS*SS*4)         // fp32 attn out
#define O_W_HI   (O_ATTO + (size_t)NROWS*EE*4)
#define O_W_LO   (O_W_HI + (size_t)4*EE*EE*2)
#define O_RS     (O_W_LO + (size_t)4*EE*EE*2)
#define SCRATCH_BYTES (O_RS + (size_t)NROWS*4)

__device__ __align__(1024) char g_scratch[SCRATCH_BYTES];

// ---------------- SMEM: 4 tiles of 128 rows x 256B (swizzled) -------------
#define TILEB 32768
#define SMEM_BYTES (4*TILEB)

__device__ __forceinline__ uint32_t smem_u32(const void* p) {
    uint32_t a;
    asm("{ .reg .u64 t; cvta.to.shared.u64 t, %1; cvt.u32.u64 %0, t; }" : "=r"(a) : "l"(p));
    return a;
}

// swizzled byte offset: row*256 + ((chunk ^ (row&7))*16), chunk = 16B unit
__device__ __forceinline__ uint32_t sw_off(int row, int chunk) {
    return (uint32_t)(row * 256 + ((chunk ^ (row & 7)) << 4));
}

// load 128x128 bf16 tile (row-major gmem, pitch elems) into swizzled SMEM
__device__ __forceinline__ void load_tile(char* dst, const __nv_bfloat16* g, int pitch) {
    int tid = threadIdx.x;
    #pragma unroll
    for (int it = 0; it < 8; it++) {
        int idx = tid + it * 256;
        int row = idx >> 4;
        int ch  = idx & 15;
        uint4 v = *reinterpret_cast<const uint4*>(g + (size_t)row * pitch + ch * 8);
        *reinterpret_cast<uint4*>(dst + sw_off(row, ch)) = v;
    }
}

__device__ __forceinline__ void ldsm4(uint32_t* r, uint32_t a) {
    asm volatile("ldmatrix.sync.aligned.m8n8.x4.shared.b16 {%0,%1,%2,%3}, [%4];"
                 : "=r"(r[0]), "=r"(r[1]), "=r"(r[2]), "=r"(r[3]) : "r"(a));
}
__device__ __forceinline__ void mma_bf16(float* c, const uint32_t* a, const uint32_t* b) {
    asm volatile(
        "mma.sync.aligned.m16n8k16.row.col.f32.bf16.bf16.f32 "
        "{%0,%1,%2,%3},{%4,%5,%6,%7},{%8,%9},{%0,%1,%2,%3};"
        : "+f"(c[0]), "+f"(c[1]), "+f"(c[2]), "+f"(c[3])
        : "r"(a[0]), "r"(a[1]), "r"(a[2]), "r"(a[3]), "r"(b[0]), "r"(b[1]));
}

// bf16x3: acc += Ah@Bh^T + Al@Bh^T + Ah@Bl^T over K=128 (tiles in SMEM)
// 8 warps: warp tile 32(m) x 64(n); wm=(wid&3)*32, wn=(wid>>2)*64
__device__ __forceinline__ void mma_tiles_x3(float acc[2][8][4],
                                             uint32_t sAh, uint32_t sAl,
                                             uint32_t sBh, uint32_t sBl) {
    int lane = threadIdx.x & 31, wid = threadIdx.x >> 5;
    int wm = (wid & 3) * 32, wn = (wid >> 2) * 64;
    int rsub  = ((lane >> 3) & 1) * 8 + (lane & 7);
    int khalf = (lane >> 4) & 1;
    #pragma unroll
    for (int pass = 0; pass < 3; pass++) {
        uint32_t sA = (pass == 1) ? sAl : sAh;
        uint32_t sB = (pass == 2) ? sBl : sBh;
        #pragma unroll
        for (int ks = 0; ks < 8; ks++) {
            int chunk = 2 * ks + khalf;
            uint32_t a[2][4];
            #pragma unroll
            for (int mt = 0; mt < 2; mt++) {
                int row = wm + mt * 16 + rsub;
                ldsm4(a[mt], sA + sw_off(row, chunk));
            }
            uint32_t b[8][2];
            #pragma unroll
            for (int nt2 = 0; nt2 < 4; nt2++) {
                int row = wn + nt2 * 16 + rsub;
                uint32_t r[4];
                ldsm4(r, sB + sw_off(row, chunk));
                b[nt2 * 2][0] = r[0]; b[nt2 * 2 + 1][0] = r[1];
                b[nt2 * 2][1] = r[2]; b[nt2 * 2 + 1][1] = r[3];
            }
            #pragma unroll
            for (int mt = 0; mt < 2; mt++)
                #pragma unroll
                for (int nt = 0; nt < 8; nt++)
                    mma_bf16(acc[mt][nt], a[mt], b[nt]);
        }
    }
}

__device__ __forceinline__ void split_bf16(float v, __nv_bfloat16& h, __nv_bfloat16& l) {
    h = __float2bfloat16(v);
    l = __float2bfloat16(v - __bfloat162float(h));
}
__device__ __forceinline__ uint32_t pack2(float a, float b) {
    __nv_bfloat162 t = __floats2bfloat162_rn(a, b);
    return *reinterpret_cast<uint32_t*>(&t);
}
__device__ __forceinline__ uint32_t pack2h(float a, float b) {
    // pack hi parts (truncation via round-to-nearest on already-representable ok)
    return pack2(a, b);
}

// ---------------------------------------------------------------------------
// weights -> bf16 hi/lo
// ---------------------------------------------------------------------------
__global__ void convert_w_kernel(const float* __restrict__ w0, const float* __restrict__ w1,
                                 const float* __restrict__ w2, const float* __restrict__ w3,
                                 __nv_bfloat16* __restrict__ hi, __nv_bfloat16* __restrict__ lo) {
    const float* src = (blockIdx.x == 0) ? w0 : (blockIdx.x == 1) ? w1 : (blockIdx.x == 2) ? w2 : w3;
    size_t base = (size_t)blockIdx.x * EE * EE;
    for (int i = threadIdx.x; i < EE * EE; i += blockDim.x) {
        float v = src[i];
        __nv_bfloat16 h, l;
        split_bf16(v, h, l);
        hi[base + i] = h;
        lo[base + i] = l;
    }
}

// ---------------------------------------------------------------------------
// LN(no affine)+ReLU -> bf16 hi/lo
// ---------------------------------------------------------------------------
__global__ __launch_bounds__(256) void ln_relu_split_kernel(const float* __restrict__ in,
                                                            __nv_bfloat16* __restrict__ hi,
                                                            __nv_bfloat16* __restrict__ lo) {
    int row  = blockIdx.x * 8 + (threadIdx.x >> 5);
    int lane = threadIdx.x & 31;
    float4 a = reinterpret_cast<const float4*>(in + (size_t)row * EE)[lane];
    float s = a.x + a.y + a.z + a.w;
    #pragma unroll
    for (int o = 16; o; o >>= 1) s += __shfl_xor_sync(0xffffffffu, s, o);
    float mean = s * (1.0f / 128.0f);
    float dx = a.x - mean, dy = a.y - mean, dz = a.z - mean, dw = a.w - mean;
    float q = dx * dx + dy * dy + dz * dz + dw * dw;
    #pragma unroll
    for (int o = 16; o; o >>= 1) q += __shfl_xor_sync(0xffffffffu, q, o);
    float inv = rsqrtf(q * (1.0f / 128.0f) + 1e-5f);
    float r0 = fmaxf(dx * inv, 0.f), r1 = fmaxf(dy * inv, 0.f);
    float r2 = fmaxf(dz * inv, 0.f), r3 = fmaxf(dw * inv, 0.f);
    __nv_bfloat16 h0, l0, h1, l1, h2, l2, h3, l3;
    split_bf16(r0, h0, l0); split_bf16(r1, h1, l1);
    split_bf16(r2, h2, l2); split_bf16(r3, h3, l3);
    uint2 uh, ul;
    uh.x = pack2(__bfloat162float(h0), __bfloat162float(h1));
    uh.y = pack2(__bfloat162float(h2), __bfloat162float(h3));
    ul.x = pack2(__bfloat162float(l0), __bfloat162float(l1));
    ul.y = pack2(__bfloat162float(l2), __bfloat162float(l3));
    *reinterpret_cast<uint2*>(hi + (size_t)row * EE + lane * 4) = uh;
    *reinterpret_cast<uint2*>(lo + (size_t)row * EE + lane * 4) = ul;
}

// ---------------------------------------------------------------------------
// adj row degree -> rsqrt
// ---------------------------------------------------------------------------
__global__ __launch_bounds__(256) void deg_kernel(const float* __restrict__ adj,
                                                  float* __restrict__ rscale) {
    int row  = blockIdx.x * 8 + (threadIdx.x >> 5);
    int lane = threadIdx.x & 31;
    const float4* p = reinterpret_cast<const float4*>(adj + (size_t)row * SS);
    float s = 0.0f;
    #pragma unroll
    for (int i = 0; i < 4; i++) {
        float4 a = p[lane + 32 * i];
        s += a.x + a.y + a.z + a.w;
    }
    #pragma unroll
    for (int o = 16; o; o >>= 1) s += __shfl_xor_sync(0xffffffffu, s, o);
    if (lane == 0) rscale[row] = rsqrtf(s);
}

// ---------------------------------------------------------------------------
// QKV MMA: grid (768, 3). y=0 Q, y=1 K (row-major hi/lo), y=2 V^T (staged)
// ---------------------------------------------------------------------------
__global__ __launch_bounds__(256, 1) void mm_qkv_kernel(
    const __nv_bfloat16* __restrict__ a_hi, const __nv_bfloat16* __restrict__ a_lo,
    const __nv_bfloat16* __restrict__ w_hi, const __nv_bfloat16* __restrict__ w_lo,
    const float* __restrict__ bq, const float* __restrict__ bk, const float* __restrict__ bv,
    __nv_bfloat16* __restrict__ qh, __nv_bfloat16* __restrict__ ql,
    __nv_bfloat16* __restrict__ kh, __nv_bfloat16* __restrict__ kl,
    __nv_bfloat16* __restrict__ vth, __nv_bfloat16* __restrict__ vtl) {
    extern __shared__ __align__(1024) char smem[];
    uint32_t sb = smem_u32(smem);
    int tid = threadIdx.x, lane = tid & 31, wid = tid >> 5;
    int y = blockIdx.y;
    int m0 = blockIdx.x * 128;
    const float* bias = (y == 0) ? bq : (y == 1) ? bk : bv;

    load_tile(smem,             a_hi + (size_t)m0 * EE, EE);
    load_tile(smem + TILEB,     a_lo + (size_t)m0 * EE, EE);
    load_tile(smem + 2 * TILEB, w_hi + (size_t)y * EE * EE, EE);
    load_tile(smem + 3 * TILEB, w_lo + (size_t)y * EE * EE, EE);
    __syncthreads();

    float acc[2][8][4];
    #pragma unroll
    for (int i = 0; i < 2; i++)
        #pragma unroll
        for (int j = 0; j < 8; j++)
            #pragma unroll
            for (int t = 0; t < 4; t++) acc[i][j][t] = 0.f;
    mma_tiles_x3(acc, sb, sb + TILEB, sb + 2 * TILEB, sb + 3 * TILEB);

    int wm = (wid & 3) * 32, wn = (wid >> 2) * 64;
    int fr = wm + (lane >> 2);
    int fc = wn + ((lane & 3) << 1);

    if (y < 2) {
        __nv_bfloat16* oh = (y == 0) ? qh : kh;
        __nv_bfloat16* ol = (y == 0) ? ql : kl;
        #pragma unroll
        for (int mt = 0; mt < 2; mt++) {
            #pragma unroll
            for (int nt = 0; nt < 8; nt++) {
                int r = fr + mt * 16;
                int c = fc + nt * 8;
                float b0 = bias[c], b1 = bias[c + 1];
                #pragma unroll
                for (int hh = 0; hh < 2; hh++) {
                    int rr = r + hh * 8;
                    float v0 = acc[mt][nt][hh * 2 + 0] + b0;
                    float v1 = acc[mt][nt][hh * 2 + 1] + b1;
                    __nv_bfloat16 h0, l0, h1, l1;
                    split_bf16(v0, h0, l0); split_bf16(v1, h1, l1);
                    size_t off = (size_t)(m0 + rr) * EE + c;
                    *reinterpret_cast<uint32_t*>(oh + off) =
                        pack2(__bfloat162float(h0), __bfloat162float(h1));
                    *reinterpret_cast<uint32_t*>(ol + off) =
                        pack2(__bfloat162float(l0), __bfloat162float(l1));
                }
            }
        }
    } else {
        // stage transposed [f][m] into smem tiles 0 (hi) and 1 (lo)
        __syncthreads();
        __nv_bfloat16* sh = reinterpret_cast<__nv_bfloat16*>(smem);
        __nv_bfloat16* sl = reinterpret_cast<__nv_bfloat16*>(smem + TILEB);
        #pragma unroll
        for (int mt = 0; mt < 2; mt++) {
            #pragma unroll
            for (int nt = 0; nt < 8; nt++) {
                int r = fr + mt * 16;
                int c = fc + nt * 8;
                float b0 = bias[c], b1 = bias[c + 1];
                #pragma unroll
                for (int hh = 0; hh < 2; hh++) {
                    int rr = r + hh * 8;
                    float v0 = acc[mt][nt][hh * 2 + 0] + b0;
                    float v1 = acc[mt][nt][hh * 2 + 1] + b1;
                    __nv_bfloat16 h, l;
                    split_bf16(v0, h, l);
                    sh[c * 128 + rr] = h; sl[c * 128 + rr] = l;
                    split_bf16(v1, h, l);
                    sh[(c + 1) * 128 + rr] = h; sl[(c + 1) * 128 + rr] = l;
                }
            }
        }
        __syncthreads();
        int b = m0 >> 9;
        int kbase = m0 & 511;
        #pragma unroll
        for (int it = 0; it < 8; it++) {
            int idx = tid + it * 256;
            int f = idx >> 4, ch = idx & 15;
            uint4 vh = *reinterpret_cast<uint4*>(sh + f * 128 + ch * 8);
            uint4 vl = *reinterpret_cast<uint4*>(sl + f * 128 + ch * 8);
            size_t off = ((size_t)b * EE + f) * SS + kbase + ch * 8;
            *reinterpret_cast<uint4*>(vth + off) = vh;
            *reinterpret_cast<uint4*>(vtl + off) = vl;
        }
    }
}

// ---------------------------------------------------------------------------
// scores MMA: grid (4 qt, 4 kt, 192 b) -> dot fp32 (scaled+masked)
// ---------------------------------------------------------------------------
__global__ __launch_bounds__(256, 1) void mm_dot_kernel(
    const __nv_bfloat16* __restrict__ qhp, const __nv_bfloat16* __restrict__ qlp,
    const __nv_bfloat16* __restrict__ khp, const __nv_bfloat16* __restrict__ klp,
    const float* __restrict__ adj, const float* __restrict__ rscale,
    float* __restrict__ dotf) {
    extern __shared__ __align__(1024) char smem[];
    uint32_t sb = smem_u32(smem);
    int tid = threadIdx.x, lane = tid & 31, wid = tid >> 5;
    int qt = blockIdx.x, kt = blockIdx.y, b = blockIdx.z;

    size_t ar = (size_t)b * SS + qt * 128;
    size_t br = (size_t)b * SS + kt * 128;
    load_tile(smem,             qhp + ar * EE, EE);
    load_tile(smem + TILEB,     qlp + ar * EE, EE);
    load_tile(smem + 2 * TILEB, khp + br * EE, EE);
    load_tile(smem + 3 * TILEB, klp + br * EE, EE);
    __syncthreads();

    float acc[2][8][4];
    #pragma unroll
    for (int i = 0; i < 2; i++)
        #pragma unroll
        for (int j = 0; j < 8; j++)
            #pragma unroll
            for (int t = 0; t < 4; t++) acc[i][j][t] = 0.f;
    mma_tiles_x3(acc, sb, sb + TILEB, sb + 2 * TILEB, sb + 3 * TILEB);

    int wm = (wid & 3) * 32, wn = (wid >> 2) * 64;
    int fr = wm + (lane >> 2);
    int fc = wn + ((lane & 3) << 1);
    #pragma unroll
    for (int mt = 0; mt < 2; mt++) {
        #pragma unroll
        for (int hh = 0; hh < 2; hh++) {
            size_t grow = ar + fr + mt * 16 + hh * 8;
            float rs = rscale[grow];
            #pragma unroll
            for (int nt = 0; nt < 8; nt++) {
                int col = kt * 128 + fc + nt * 8;
                float2 av = *reinterpret_cast<const float2*>(adj + grow * SS + col);
                float v0 = (av.x != 0.f) ? acc[mt][nt][hh * 2 + 0] * rs : -1e30f;
                float v1 = (av.y != 0.f) ? acc[mt][nt][hh * 2 + 1] * rs : -1e30f;
                *reinterpret_cast<float2*>(dotf + grow * SS + col) = make_float2(v0, v1);
            }
        }
    }
}

// ---------------------------------------------------------------------------
// softmax: fp32 scores -> P bf16 hi/lo. One warp per row.
// ---------------------------------------------------------------------------
__global__ __launch_bounds__(256) void softmax_kernel(const float* __restrict__ dotf,
                                                      __nv_bfloat16* __restrict__ ph,
                                                      __nv_bfloat16* __restrict__ pl) {
    int row  = blockIdx.x * 8 + (threadIdx.x >> 5);
    int lane = threadIdx.x & 31;
    const float4* p = reinterpret_cast<const float4*>(dotf + (size_t)row * SS);
    float4 v[4];
    float m = -3.4e38f;
    #pragma unroll
    for (int i = 0; i < 4; i++) {
        v[i] = p[lane + 32 * i];
        m = fmaxf(m, fmaxf(fmaxf(v[i].x, v[i].y), fmaxf(v[i].z, v[i].w)));
    }
    #pragma unroll
    for (int o = 16; o; o >>= 1) m = fmaxf(m, __shfl_xor_sync(0xffffffffu, m, o));
    float s = 0.f;
    #pragma unroll
    for (int i = 0; i < 4; i++) {
        v[i].x = __expf(v[i].x - m); v[i].y = __expf(v[i].y - m);
        v[i].z = __expf(v[i].z - m); v[i].w = __expf(v[i].w - m);
        s += v[i].x + v[i].y + v[i].z + v[i].w;
    }
    #pragma unroll
    for (int o = 16; o; o >>= 1) s += __shfl_xor_sync(0xffffffffu, s, o);
    float inv = 1.f / s;
    #pragma unroll
    for (int i = 0; i < 4; i++) {
        float p0 = v[i].x * inv, p1 = v[i].y * inv, p2 = v[i].z * inv, p3 = v[i].w * inv;
        __nv_bfloat16 h0, l0, h1, l1, h2, l2, h3, l3;
        split_bf16(p0, h0, l0); split_bf16(p1, h1, l1);
        split_bf16(p2, h2, l2); split_bf16(p3, h3, l3);
        uint2 uh, ul;
        uh.x = pack2(__bfloat162float(h0), __bfloat162float(h1));
        uh.y = pack2(__bfloat162float(h2), __bfloat162float(h3));
        ul.x = pack2(__bfloat162float(l0), __bfloat162float(l1));
        ul.y = pack2(__bfloat162float(l2), __bfloat162float(l3));
        size_t off = (size_t)row * SS + (lane + 32 * i) * 4;
        *reinterpret_cast<uint2*>(ph + off) = uh;
        *reinterpret_cast<uint2*>(pl + off) = ul;
    }
}

// ---------------------------------------------------------------------------
// attn @ V MMA: grid (4 qt, 192 b). K=512 in 4 chunks.
// ---------------------------------------------------------------------------
__global__ __launch_bounds__(256, 1) void mm_av_kernel(
    const __nv_bfloat16* __restrict__ ph, const __nv_bfloat16* __restrict__ pl,
    const __nv_bfloat16* __restrict__ vth, const __nv_bfloat16* __restrict__ vtl,
    float* __restrict__ att) {
    extern __shared__ __align__(1024) char smem[];
    uint32_t sb = smem_u32(smem);
    int tid = threadIdx.x, lane = tid & 31, wid = tid >> 5;
    int qt = blockIdx.x, b = blockIdx.y;

    size_t prow0 = (size_t)b * SS + qt * 128;
    float acc[2][8][4];
    #pragma unroll
    for (int i = 0; i < 2; i++)
        #pragma unroll
        for (int j = 0; j < 8; j++)
            #pragma unroll
            for (int t = 0; t < 4; t++) acc[i][j][t] = 0.f;

    for (int kc = 0; kc < 4; kc++) {
        load_tile(smem,             ph + prow0 * SS + kc * 128, SS);
        load_tile(smem + TILEB,     pl + prow0 * SS + kc * 128, SS);
        load_tile(smem + 2 * TILEB, vth + (size_t)b * EE * SS + kc * 128, SS);
        load_tile(smem + 3 * TILEB, vtl + (size_t)b * EE * SS + kc * 128, SS);
        __syncthreads();
        mma_tiles_x3(acc, sb, sb + TILEB, sb + 2 * TILEB, sb + 3 * TILEB);
        __syncthreads();
    }

    int wm = (wid & 3) * 32, wn = (wid >> 2) * 64;
    int fr = wm + (lane >> 2);
    int fc = wn + ((lane & 3) << 1);
    #pragma unroll
    for (int mt = 0; mt < 2; mt++) {
        #pragma unroll
        for (int hh = 0; hh < 2; hh++) {
            size_t gm = prow0 + fr + mt * 16 + hh * 8;
            #pragma unroll
            for (int nt = 0; nt < 8; nt++) {
                int c = fc + nt * 8;
                *reinterpret_cast<float2*>(att + gm * EE + c) =
                    make_float2(acc[mt][nt][hh * 2 + 0], acc[mt][nt][hh * 2 + 1]);
            }
        }
    }
}

// ---------------------------------------------------------------------------
// out projection MMA: out = x + hs @ Wo^T + bo. grid (768).
// ---------------------------------------------------------------------------
__global__ __launch_bounds__(256, 1) void mm_out_kernel(
    const __nv_bfloat16* __restrict__ a_hi, const __nv_bfloat16* __restrict__ a_lo,
    const __nv_bfloat16* __restrict__ w_hi, const __nv_bfloat16* __restrict__ w_lo,
    const float* __restrict__ bo, const float* __restrict__ x,
    float* __restrict__ out) {
    extern __shared__ __align__(1024) char smem[];
    uint32_t sb = smem_u32(smem);
    int tid = threadIdx.x, lane = tid & 31, wid = tid >> 5;
    int m0 = blockIdx.x * 128;

    load_tile(smem,             a_hi + (size_t)m0 * EE, EE);
    load_tile(smem + TILEB,     a_lo + (size_t)m0 * EE, EE);
    load_tile(smem + 2 * TILEB, w_hi, EE);
    load_tile(smem + 3 * TILEB, w_lo, EE);
    __syncthreads();

    float acc[2][8][4];
    #pragma unroll
    for (int i = 0; i < 2; i++)
        #pragma unroll
        for (int j = 0; j < 8; j++)
            #pragma unroll
            for (int t = 0; t < 4; t++) acc[i][j][t] = 0.f;
    mma_tiles_x3(acc, sb, sb + TILEB, sb + 2 * TILEB, sb + 3 * TILEB);

    int wm = (wid & 3) * 32, wn = (wid >> 2) * 64;
    int fr = wm + (lane >> 2);
    int fc = wn + ((lane & 3) << 1);
    #pragma unroll
    for (int mt = 0; mt < 2; mt++) {
        #pragma unroll
        for (int hh = 0; hh < 2; hh++) {
            size_t gm = (size_t)(m0 + fr + mt * 16 + hh * 8);
            #pragma unroll
            for (int nt = 0; nt < 8; nt++) {
                int c = fc + nt * 8;
                float2 xr = *reinterpret_cast<const float2*>(x + gm * EE + c);
                float v0 = acc[mt][nt][hh * 2 + 0] + bo[c] + xr.x;
                float v1 = acc[mt][nt][hh * 2 + 1] + bo[c + 1] + xr.y;
                *reinterpret_cast<float2*>(out + gm * EE + c) = make_float2(v0, v1);
            }
        }
    }
}

// ---------------------------------------------------------------------------
extern "C" void kernel_launch(void* const* d_in, const int* in_sizes, int n_in,
                              void* d_out, int out_size) {
    const float* x   = (const float*)d_in[0];
    const float* adj = (const float*)d_in[1];
    const float* Wq  = (const float*)d_in[2];
    const float* bq  = (const float*)d_in[3];
    const float* Wk  = (const float*)d_in[4];
    const float* bk  = (const float*)d_in[5];
    const float* Wv  = (const float*)d_in[6];
    const float* bv  = (const float*)d_in[7];
    const float* Wo  = (const float*)d_in[8];
    const float* bo  = (const float*)d_in[9];
    float* out = (float*)d_out;

    char* s = nullptr;
    cudaGetSymbolAddress((void**)&s, g_scratch);
    __nv_bfloat16* xs_hi = (__nv_bfloat16*)(s + O_XS_HI);
    __nv_bfloat16* xs_lo = (__nv_bfloat16*)(s + O_XS_LO);
    __nv_bfloat16* q_hi  = (__nv_bfloat16*)(s + O_Q_HI);
    __nv_bfloat16* q_lo  = (__nv_bfloat16*)(s + O_Q_LO);
    __nv_bfloat16* k_hi  = (__nv_bfloat16*)(s + O_K_HI);
    __nv_bfloat16* k_lo  = (__nv_bfloat16*)(s + O_K_LO);
    __nv_bfloat16* vt_hi = (__nv_bfloat16*)(s + O_VT_HI);
    __nv_bfloat16* vt_lo = (__nv_bfloat16*)(s + O_VT_LO);
    __nv_bfloat16* hs_hi = (__nv_bfloat16*)(s + O_HS_HI);
    __nv_bfloat16* hs_lo = (__nv_bfloat16*)(s + O_HS_LO);
    __nv_bfloat16* ph    = (__nv_bfloat16*)(s + O_PH);
    __nv_bfloat16* pl    = (__nv_bfloat16*)(s + O_PL);
    float*         dotf  = (float*)(s + O_DOT);
    float*         attf  = (float*)(s + O_ATTO);
    __nv_bfloat16* w_hi  = (__nv_bfloat16*)(s + O_W_HI);
    __nv_bfloat16* w_lo  = (__nv_bfloat16*)(s + O_W_LO);
    float*         rs    = (float*)(s + O_RS);

    cudaFuncSetAttribute(mm_qkv_kernel, cudaFuncAttributeMaxDynamicSharedMemorySize, SMEM_BYTES);
    cudaFuncSetAttribute(mm_dot_kernel, cudaFuncAttributeMaxDynamicSharedMemorySize, SMEM_BYTES);
    cudaFuncSetAttribute(mm_av_kernel,  cudaFuncAttributeMaxDynamicSharedMemorySize, SMEM_BYTES);
    cudaFuncSetAttribute(mm_out_kernel, cudaFuncAttributeMaxDynamicSharedMemorySize, SMEM_BYTES);

    convert_w_kernel<<<4, 256>>>(Wq, Wk, Wv, Wo, w_hi, w_lo);
    ln_relu_split_kernel<<<NROWS / 8, 256>>>(x, xs_hi, xs_lo);
    deg_kernel<<<NROWS / 8, 256>>>(adj, rs);
    mm_qkv_kernel<<<dim3(NROWS / 128, 3), 256, SMEM_BYTES>>>(
        xs_hi, xs_lo, w_hi, w_lo, bq, bk, bv,
        q_hi, q_lo, k_hi, k_lo, vt_hi, vt_lo);
    mm_dot_kernel<<<dim3(4, 4, NB), 256, SMEM_BYTES>>>(
        q_hi, q_lo, k_hi, k_lo, adj, rs, dotf);
    softmax_kernel<<<NROWS / 8, 256>>>(dotf, ph, pl);
    mm_av_kernel<<<dim3(4, NB), 256, SMEM_BYTES>>>(ph, pl, vt_hi, vt_lo, attf);
    ln_relu_split_kernel<<<NROWS / 8, 256>>>(attf, hs_hi, hs_lo);
    mm_out_kernel<<<NROWS / 128, 256, SMEM_BYTES>>>(
        hs_hi, hs_lo, w_hi + 3 * EE * EE, w_lo + 3 * EE * EE, bo, x, out);
}